// round 6
// baseline (speedup 1.0000x reference)
#include <cuda_runtime.h>
#include <cstdint>
#include <cstddef>

#define N_NODES 100000
#define N_EDGES 1600000
#define F_IN    64
#define HIDDEN  128
#define N_GRAPHS 1024
#define EPS 1e-5f

#define SCAN_BLK 256
#define N_SCAN_BLOCKS ((N_NODES + SCAN_BLK - 1) / SCAN_BLK)   // 391

// ---------------- static scratch (no allocation allowed) ----------------
__device__ float g_hr[(size_t)N_NODES * HIDDEN];
__device__ float g_ho[(size_t)N_NODES * HIDDEN];
__device__ float g_ha[(size_t)N_NODES * HIDDEN];
__device__ float g_hb[(size_t)N_NODES * HIDDEN];

__device__ float g_scale[3][HIDDEN];
__device__ float g_shift[3][HIDDEN];

// packed-k interleaved weights: per layer, float2[K/2][256] (cols 0..127 = Wr, 128..255 = Wo)
__device__ __align__(16) float2 g_Wp[8192 + 16384 + 16384];

__device__ int   g_deg[N_NODES];
__device__ int   g_incl[N_SCAN_BLOCKS * SCAN_BLK];
__device__ int   g_bsum[N_SCAN_BLOCKS];
__device__ int   g_boff[N_SCAN_BLOCKS];
__device__ int   g_rowptr[N_NODES + 1];
__device__ int   g_cursor[N_NODES];
__device__ int   g_csr_src[N_EDGES];
__device__ float g_csr_ew[N_EDGES];

// packed dual-lane FMA: acc.lo += a.lo*b.lo ; acc.hi += a.hi*b.hi
#define FMA2(acc, a, b) \
    asm("fma.rn.f32x2 %0, %1, %2, %0;" : "+l"(acc) : "l"(a), "l"(b))

// ======================= CSR build (by dst) ==============================
__global__ void hist_kernel(const int* __restrict__ dst, int* __restrict__ deg)
{
    int e = blockIdx.x * blockDim.x + threadIdx.x;
    if (e < N_EDGES) atomicAdd(deg + __ldg(dst + e), 1);
}

__global__ void scan1_kernel(const int* __restrict__ deg,
                             int* __restrict__ incl, int* __restrict__ bsum)
{
    __shared__ int s[SCAN_BLK];
    int gid = blockIdx.x * SCAN_BLK + threadIdx.x;
    int v = (gid < N_NODES) ? deg[gid] : 0;
    s[threadIdx.x] = v;
    __syncthreads();
    #pragma unroll
    for (int off = 1; off < SCAN_BLK; off <<= 1) {
        int t = (threadIdx.x >= off) ? s[threadIdx.x - off] : 0;
        __syncthreads();
        s[threadIdx.x] += t;
        __syncthreads();
    }
    incl[gid] = s[threadIdx.x];
    if (threadIdx.x == SCAN_BLK - 1) bsum[blockIdx.x] = s[threadIdx.x];
}

__global__ void scan2_kernel(const int* __restrict__ bsum, int* __restrict__ boff)
{
    __shared__ int s[512];
    int t = threadIdx.x;
    s[t] = (t < N_SCAN_BLOCKS) ? bsum[t] : 0;
    __syncthreads();
    #pragma unroll
    for (int off = 1; off < 512; off <<= 1) {
        int v = (t >= off) ? s[t - off] : 0;
        __syncthreads();
        s[t] += v;
        __syncthreads();
    }
    if (t < N_SCAN_BLOCKS) boff[t] = s[t] - bsum[t];
}

__global__ void scan3_kernel(const int* __restrict__ deg,
                             const int* __restrict__ incl,
                             const int* __restrict__ boff,
                             int* __restrict__ rowptr)
{
    int i = blockIdx.x * blockDim.x + threadIdx.x;
    if (i < N_NODES)
        rowptr[i] = incl[i] - deg[i] + boff[i / SCAN_BLK];
    if (i == 0) rowptr[N_NODES] = N_EDGES;
}

__global__ void fill_kernel(const int* __restrict__ src,
                            const int* __restrict__ dst,
                            const float* __restrict__ ew,
                            const int* __restrict__ rowptr,
                            int* __restrict__ cursor,
                            int* __restrict__ csr_src,
                            float* __restrict__ csr_ew)
{
    int e = blockIdx.x * blockDim.x + threadIdx.x;
    if (e >= N_EDGES) return;
    int d = __ldg(dst + e);
    int pos = atomicAdd(cursor + d, 1);
    int idx = __ldg(rowptr + d) + pos;
    csr_src[idx] = __ldg(src + e);
    csr_ew[idx]  = __ldg(ew + e);
}

// ---------------- fold BN params (+rel bias) into scale/shift -------------
__global__ void bn_fold_kernel(const float* __restrict__ br0, const float* __restrict__ g0,
                               const float* __restrict__ b0,  const float* __restrict__ m0,
                               const float* __restrict__ v0,
                               const float* __restrict__ br1, const float* __restrict__ g1,
                               const float* __restrict__ b1,  const float* __restrict__ m1,
                               const float* __restrict__ v1,
                               const float* __restrict__ br2, const float* __restrict__ g2,
                               const float* __restrict__ b2,  const float* __restrict__ m2,
                               const float* __restrict__ v2)
{
    int j = threadIdx.x;
    int l = blockIdx.x;
    const float* br = (l == 0) ? br0 : (l == 1) ? br1 : br2;
    const float* g  = (l == 0) ? g0  : (l == 1) ? g1  : g2;
    const float* b  = (l == 0) ? b0  : (l == 1) ? b1  : b2;
    const float* m  = (l == 0) ? m0  : (l == 1) ? m1  : m2;
    const float* v  = (l == 0) ? v0  : (l == 1) ? v1  : v2;
    float s = g[j] * rsqrtf(v[j] + EPS);
    g_scale[l][j] = s;
    g_shift[l][j] = (br[j] - m[j]) * s + b[j];
}

// -------- prep: interleave weights into packed-k images ------------------
__global__ void prep_weights_kernel(const float* __restrict__ Wr0, const float* __restrict__ Wo0,
                                    const float* __restrict__ Wr1, const float* __restrict__ Wo1,
                                    const float* __restrict__ Wr2, const float* __restrict__ Wo2)
{
    int idx = blockIdx.x * blockDim.x + threadIdx.x;
    int total = 8192 + 16384 + 16384;
    if (idx >= total) return;
    int l, rem, base;
    if (idx < 8192)                { l = 0; rem = idx;          base = 0; }
    else if (idx < 8192 + 16384)   { l = 1; rem = idx - 8192;   base = 8192; }
    else                           { l = 2; rem = idx - 24576;  base = 24576; }
    int k2 = rem / 256;
    int j  = rem % 256;
    int jj = j & 127;
    const float* Wr = (l == 0) ? Wr0 : (l == 1) ? Wr1 : Wr2;
    const float* Wo = (l == 0) ? Wo0 : (l == 1) ? Wo1 : Wo2;
    const float* W  = (j < 128) ? Wr : Wo;
    float2 p;
    p.x = __ldg(W + (2 * k2 + 0) * 128 + jj);
    p.y = __ldg(W + (2 * k2 + 1) * 128 + jj);
    g_Wp[base + rem] = p;
}

// ====== dual GEMM via packed FFMA2: hr = h@Wr, ho = h@Wo ==================
template <int K>
__global__ __launch_bounds__(128, 3)
void gemm_dual2_kernel(const float* __restrict__ h,
                       const unsigned long long* __restrict__ Wp,
                       float* __restrict__ hr,
                       float* __restrict__ ho)
{
    __shared__ unsigned long long sH[32 * (K / 2)];   // = 32*K floats
    const int tid = threadIdx.x;
    const int n0  = blockIdx.x * 32;

    {
        const uint4* hp = reinterpret_cast<const uint4*>(h + (size_t)n0 * K);
        uint4* s4 = reinterpret_cast<uint4*>(sH);
        #pragma unroll
        for (int i = tid; i < 32 * K / 4; i += 128) s4[i] = hp[i];   // FIXED bound
    }
    __syncthreads();

    unsigned long long rAcc[32], oAcc[32];
    #pragma unroll
    for (int mm = 0; mm < 32; mm++) { rAcc[mm] = 0ull; oAcc[mm] = 0ull; }

    // 4 k-values (= 2 packed pairs) per iteration
    for (int k2 = 0; k2 < K / 2; k2 += 2) {
        unsigned long long wr0 = __ldg(Wp + (size_t)(k2 + 0) * 256 + tid);
        unsigned long long wr1 = __ldg(Wp + (size_t)(k2 + 1) * 256 + tid);
        unsigned long long wo0 = __ldg(Wp + (size_t)(k2 + 0) * 256 + 128 + tid);
        unsigned long long wo1 = __ldg(Wp + (size_t)(k2 + 1) * 256 + 128 + tid);
        #pragma unroll
        for (int mm = 0; mm < 32; mm++) {
            ulonglong2 a = *reinterpret_cast<const ulonglong2*>(&sH[mm * (K / 2) + k2]);
            FMA2(rAcc[mm], a.x, wr0);
            FMA2(rAcc[mm], a.y, wr1);
            FMA2(oAcc[mm], a.x, wo0);
            FMA2(oAcc[mm], a.y, wo1);
        }
    }

    #pragma unroll
    for (int mm = 0; mm < 32; mm++) {
        float r = __uint_as_float((uint32_t)rAcc[mm]) +
                  __uint_as_float((uint32_t)(rAcc[mm] >> 32));
        float o = __uint_as_float((uint32_t)oAcc[mm]) +
                  __uint_as_float((uint32_t)(oAcc[mm] >> 32));
        hr[(size_t)(n0 + mm) * HIDDEN + tid] = r;
        ho[(size_t)(n0 + mm) * HIDDEN + tid] = o;
    }
}

// === fused gather + root + BN + ReLU:  out = relu((Σ ew*hr[src] + ho)*s + t)
__global__ void gather_fused_kernel(const float* __restrict__ hr,
                                    const float* __restrict__ ho,
                                    const int* __restrict__ rowptr,
                                    const int* __restrict__ csr_src,
                                    const float* __restrict__ csr_ew,
                                    const float* __restrict__ scale,
                                    const float* __restrict__ shift,
                                    float* __restrict__ out)
{
    int node = (blockIdx.x * blockDim.x + threadIdx.x) >> 5;
    if (node >= N_NODES) return;
    int lane = threadIdx.x & 31;
    int beg = __ldg(rowptr + node);
    int end = __ldg(rowptr + node + 1);

    const float4* hr4 = reinterpret_cast<const float4*>(hr);
    float4 acc = *(reinterpret_cast<const float4*>(ho + (size_t)node * 128) + lane);

    int i = beg;
    for (; i + 3 < end; i += 4) {
        int   s0 = __ldg(csr_src + i);
        int   s1 = __ldg(csr_src + i + 1);
        int   s2 = __ldg(csr_src + i + 2);
        int   s3 = __ldg(csr_src + i + 3);
        float e0 = __ldg(csr_ew + i);
        float e1 = __ldg(csr_ew + i + 1);
        float e2 = __ldg(csr_ew + i + 2);
        float e3 = __ldg(csr_ew + i + 3);
        float4 v0 = hr4[(size_t)s0 * 32 + lane];
        float4 v1 = hr4[(size_t)s1 * 32 + lane];
        float4 v2 = hr4[(size_t)s2 * 32 + lane];
        float4 v3 = hr4[(size_t)s3 * 32 + lane];
        acc.x = fmaf(v0.x, e0, acc.x); acc.y = fmaf(v0.y, e0, acc.y);
        acc.z = fmaf(v0.z, e0, acc.z); acc.w = fmaf(v0.w, e0, acc.w);
        acc.x = fmaf(v1.x, e1, acc.x); acc.y = fmaf(v1.y, e1, acc.y);
        acc.z = fmaf(v1.z, e1, acc.z); acc.w = fmaf(v1.w, e1, acc.w);
        acc.x = fmaf(v2.x, e2, acc.x); acc.y = fmaf(v2.y, e2, acc.y);
        acc.z = fmaf(v2.z, e2, acc.z); acc.w = fmaf(v2.w, e2, acc.w);
        acc.x = fmaf(v3.x, e3, acc.x); acc.y = fmaf(v3.y, e3, acc.y);
        acc.z = fmaf(v3.z, e3, acc.z); acc.w = fmaf(v3.w, e3, acc.w);
    }
    for (; i < end; i++) {
        int   s0 = __ldg(csr_src + i);
        float e0 = __ldg(csr_ew + i);
        float4 v0 = hr4[(size_t)s0 * 32 + lane];
        acc.x = fmaf(v0.x, e0, acc.x); acc.y = fmaf(v0.y, e0, acc.y);
        acc.z = fmaf(v0.z, e0, acc.z); acc.w = fmaf(v0.w, e0, acc.w);
    }

    float4 sc = *(reinterpret_cast<const float4*>(scale) + lane);
    float4 sh = *(reinterpret_cast<const float4*>(shift) + lane);
    float4 res;
    res.x = fmaxf(fmaf(acc.x, sc.x, sh.x), 0.f);
    res.y = fmaxf(fmaf(acc.y, sc.y, sh.y), 0.f);
    res.z = fmaxf(fmaf(acc.z, sc.z, sh.z), 0.f);
    res.w = fmaxf(fmaf(acc.w, sc.w, sh.w), 0.f);
    *(reinterpret_cast<float4*>(out + (size_t)node * 128) + lane) = res;
}

// ------------- fused mean-pool + head (block per graph) ------------------
__global__ void pool_head_kernel(const float* __restrict__ h,
                                 const int* __restrict__ batch,
                                 const float* __restrict__ W1,
                                 const float* __restrict__ b1,
                                 const float* __restrict__ W2,
                                 const float* __restrict__ b2,
                                 float* __restrict__ out)
{
    __shared__ float sp[HIDDEN];
    __shared__ float sred[128];
    __shared__ int srange[2];
    const int g = blockIdx.x;
    const int t = threadIdx.x;

    if (t < 2) {
        int key = g + t;
        int lo = 0, hi = N_NODES;
        while (lo < hi) {
            int mid = (lo + hi) >> 1;
            if (__ldg(batch + mid) < key) lo = mid + 1; else hi = mid;
        }
        srange[t] = lo;
    }
    __syncthreads();
    const int start = srange[0];
    const int end   = srange[1];

    float sum = 0.f;
    for (int n = start; n < end; n++)
        sum += h[(size_t)n * HIDDEN + t];
    float inv = 1.0f / fmaxf((float)(end - start), 1.0f);
    sp[t] = sum * inv;
    __syncthreads();

    float val = 0.f;
    if (t < 64) {
        float acc = __ldg(b1 + t);
        #pragma unroll 8
        for (int k = 0; k < HIDDEN; k++)
            acc = fmaf(sp[k], __ldg(W1 + k * 64 + t), acc);
        val = fmaxf(acc, 0.f) * __ldg(W2 + t);
    }
    sred[t] = val;
    __syncthreads();
    for (int s = 64; s > 0; s >>= 1) {
        if (t < s) sred[t] += sred[t + s];
        __syncthreads();
    }
    if (t == 0) out[g] = sred[0] + __ldg(b2);
}

// -------------------------------------------------------------------------
extern "C" void kernel_launch(void* const* d_in, const int* in_sizes, int n_in,
                              void* d_out, int out_size)
{
    (void)in_sizes; (void)n_in; (void)out_size;
    const float* x     = (const float*)d_in[0];
    const int*   ei    = (const int*)  d_in[1];
    const float* ea    = (const float*)d_in[2];
    const int*   batch = (const int*)  d_in[3];
    const float* P[21];
    for (int i = 0; i < 21; i++) P[i] = (const float*)d_in[4 + i];
    const float* head_w1 = (const float*)d_in[25];
    const float* head_b1 = (const float*)d_in[26];
    const float* head_w2 = (const float*)d_in[27];
    const float* head_b2 = (const float*)d_in[28];
    float* out = (float*)d_out;

    float *hr, *ho, *ha, *hb, *scale, *shift;
    unsigned long long* Wp;
    int *deg, *incl, *bsum, *boff, *rowptr, *cursor, *csr_src;
    float *csr_ew;
    cudaGetSymbolAddress((void**)&hr,      g_hr);
    cudaGetSymbolAddress((void**)&ho,      g_ho);
    cudaGetSymbolAddress((void**)&ha,      g_ha);
    cudaGetSymbolAddress((void**)&hb,      g_hb);
    cudaGetSymbolAddress((void**)&scale,   g_scale);
    cudaGetSymbolAddress((void**)&shift,   g_shift);
    cudaGetSymbolAddress((void**)&Wp,      g_Wp);
    cudaGetSymbolAddress((void**)&deg,     g_deg);
    cudaGetSymbolAddress((void**)&incl,    g_incl);
    cudaGetSymbolAddress((void**)&bsum,    g_bsum);
    cudaGetSymbolAddress((void**)&boff,    g_boff);
    cudaGetSymbolAddress((void**)&rowptr,  g_rowptr);
    cudaGetSymbolAddress((void**)&cursor,  g_cursor);
    cudaGetSymbolAddress((void**)&csr_src, g_csr_src);
    cudaGetSymbolAddress((void**)&csr_ew,  g_csr_ew);

    const int* src = ei;
    const int* dst = ei + N_EDGES;

    // ---- Build CSR by destination + fold BN + pack weights ----
    cudaMemsetAsync(deg,    0, N_NODES * sizeof(int), 0);
    cudaMemsetAsync(cursor, 0, N_NODES * sizeof(int), 0);
    hist_kernel<<<(N_EDGES + 255) / 256, 256>>>(dst, deg);
    scan1_kernel<<<N_SCAN_BLOCKS, SCAN_BLK>>>(deg, incl, bsum);
    scan2_kernel<<<1, 512>>>(bsum, boff);
    scan3_kernel<<<(N_NODES + 255) / 256, 256>>>(deg, incl, boff, rowptr);
    fill_kernel<<<(N_EDGES + 255) / 256, 256>>>(src, dst, ea, rowptr, cursor,
                                                csr_src, csr_ew);
    bn_fold_kernel<<<3, 128>>>(P[1], P[3], P[4], P[5], P[6],
                               P[8], P[10], P[11], P[12], P[13],
                               P[15], P[17], P[18], P[19], P[20]);
    prep_weights_kernel<<<(8192 + 16384 + 16384 + 255) / 256, 256>>>(
        P[0], P[2], P[7], P[9], P[14], P[16]);

    const int gather_blocks = (N_NODES * 32 + 255) / 256;
    const int gemm_blocks   = N_NODES / 32;                 // 3125

    // ---- Layer 0: x(K=64) -> hr,ho -> gather -> ha ----
    gemm_dual2_kernel<64><<<gemm_blocks, 128>>>(x, Wp, hr, ho);
    gather_fused_kernel<<<gather_blocks, 256>>>(hr, ho, rowptr, csr_src, csr_ew,
                                                scale + 0 * HIDDEN, shift + 0 * HIDDEN, ha);

    // ---- Layer 1: ha(K=128) -> hr,ho -> gather -> hb ----
    gemm_dual2_kernel<128><<<gemm_blocks, 128>>>(ha, Wp + 8192, hr, ho);
    gather_fused_kernel<<<gather_blocks, 256>>>(hr, ho, rowptr, csr_src, csr_ew,
                                                scale + 1 * HIDDEN, shift + 1 * HIDDEN, hb);

    // ---- Layer 2: hb(K=128) -> hr,ho -> gather -> ha ----
    gemm_dual2_kernel<128><<<gemm_blocks, 128>>>(hb, Wp + 24576, hr, ho);
    gather_fused_kernel<<<gather_blocks, 256>>>(hr, ho, rowptr, csr_src, csr_ew,
                                                scale + 2 * HIDDEN, shift + 2 * HIDDEN, ha);

    // ---- Fused mean pool + head ----
    pool_head_kernel<<<N_GRAPHS, 128>>>(ha, batch, head_w1, head_b1,
                                        head_w2, head_b2, out);
}